// round 1
// baseline (speedup 1.0000x reference)
#include <cuda_runtime.h>
#include <math.h>

// Problem constants (from reference)
#define NH 16
#define ND 64
#define SEG_LEN 128

// ---------------------------------------------------------------------------
// Kernel 1: zero the entire output (134 MB, store-bandwidth bound)
// ---------------------------------------------------------------------------
__global__ void zero_kernel(float4* __restrict__ out, int nvec) {
    int idx = blockIdx.x * blockDim.x + threadIdx.x;
    if (idx < nvec) {
        out[idx] = make_float4(0.f, 0.f, 0.f, 0.f);
    }
}

// ---------------------------------------------------------------------------
// Kernel 2: dilated attention over the two 128-query segments.
// One warp per (seg*128 + i, h). 32 lanes, each lane owns dims {lane, lane+32}.
// Online softmax over keys; kpos = i + j*step is monotone increasing, so with
// is_causal we can break at the first masked key. Masked keys contribute
// exp(-1e30 - max) == 0.0f exactly in fp32, so skipping them is bit-equivalent
// to the reference softmax.
// ---------------------------------------------------------------------------
__global__ void attn_kernel(const float* __restrict__ q,
                            const float* __restrict__ k,
                            const float* __restrict__ v,
                            const int* __restrict__ is_causal_ptr,
                            float* __restrict__ out) {
    const int qh  = blockIdx.x;        // 0..255  (seg*128 + i)
    const int h   = blockIdx.y;        // 0..15
    const int seg = qh >> 7;           // 0 or 1
    const int i   = qh & 127;
    const int seg_start = seg * SEG_LEN;
    const int step = SEG_LEN << seg;   // 128 for seg 0, 256 for seg 1
    const int qpos = seg_start + i;
    const int lane = threadIdx.x;      // 0..31
    const int causal = is_causal_ptr[0];

    const float scale = 0.125f;        // 1/sqrt(64)

    const size_t qbase = ((size_t)qpos * NH + h) * ND;
    const float q0 = q[qbase + lane];
    const float q1 = q[qbase + lane + 32];

    float m = -INFINITY;
    float l = 0.f;
    float acc0 = 0.f, acc1 = 0.f;

    for (int j = 0; j < SEG_LEN; j++) {
        const int kpos = i + j * step;
        if (causal && kpos > qpos) break;   // monotone -> all later keys masked

        const size_t kb = ((size_t)kpos * NH + h) * ND;
        float s = q0 * k[kb + lane] + q1 * k[kb + lane + 32];
        // warp allreduce (32 lanes)
        #pragma unroll
        for (int off = 16; off; off >>= 1)
            s += __shfl_xor_sync(0xffffffffu, s, off);
        s *= scale;

        const float mnew = fmaxf(m, s);
        const float corr = expf(m - mnew);     // 0 on first iter (m = -inf)
        const float p    = expf(s - mnew);
        l    = l * corr + p;
        acc0 = acc0 * corr + p * v[kb + lane];
        acc1 = acc1 * corr + p * v[kb + lane + 32];
        m = mnew;
    }

    const float inv = 1.f / l;
    out[qbase + lane]      = acc0 * inv;
    out[qbase + lane + 32] = acc1 * inv;
}

// ---------------------------------------------------------------------------
// Launch
// ---------------------------------------------------------------------------
extern "C" void kernel_launch(void* const* d_in, const int* in_sizes, int n_in,
                              void* d_out, int out_size) {
    const float* q = (const float*)d_in[0];
    const float* k = (const float*)d_in[1];
    const float* v = (const float*)d_in[2];
    const int* is_causal = (const int*)d_in[3];
    float* out = (float*)d_out;

    // out_size = 1*32768*16*64 = 33554432 floats, divisible by 4
    const int nvec = out_size / 4;
    const int threads = 256;
    const int blocks = (nvec + threads - 1) / threads;
    zero_kernel<<<blocks, threads>>>((float4*)out, nvec);

    dim3 grid(256, NH);
    attn_kernel<<<grid, 32>>>(q, k, v, is_causal, out);
}

// round 3
// speedup vs baseline: 1.0530x; 1.0530x over previous
#include <cuda_runtime.h>
#include <math.h>

#define NH 16
#define ND 64
#define SEG_LEN 128

// Attention region: rows 0..255  ->  256*NH*ND floats = 262144 (1 MB)
#define ATTN_FLOATS (256 * NH * ND)

#define ATTN_BLOCKS 512   // 8 warps/block * 512 = 4096 warps = one per (q,h)
#define ZERO_BLOCKS 1536
#define THREADS 256

// ---------------------------------------------------------------------------
// Fused kernel:
//   blocks [0, ATTN_BLOCKS)             -> dilated attention (writes rows 0..255)
//   blocks [ATTN_BLOCKS, +ZERO_BLOCKS)  -> zero-fill the rest of the output
// The two regions are disjoint, so they run fully concurrently in one launch.
// ---------------------------------------------------------------------------
__global__ void fused_kernel(const float* __restrict__ q,
                             const float* __restrict__ k,
                             const float* __restrict__ v,
                             const int* __restrict__ is_causal_ptr,
                             float* __restrict__ out,
                             int out_elems) {
    if (blockIdx.x < ATTN_BLOCKS) {
        // ------------------- attention path -------------------
        const int w    = blockIdx.x * (THREADS / 32) + (threadIdx.x >> 5); // 0..4095
        const int lane = threadIdx.x & 31;
        const int qh   = w & 255;          // seg*128 + i
        const int h    = w >> 8;           // 0..15
        const int seg  = qh >> 7;
        const int i    = qh & 127;
        const int seg_start = seg * SEG_LEN;
        const int step = SEG_LEN << seg;   // 128 (seg 0) or 256 (seg 1)
        const int qpos = seg_start + i;
        const int causal = is_causal_ptr[0];
        const float scale = 0.125f;        // 1/sqrt(64)

        const size_t qbase = ((size_t)qpos * NH + h) * ND;
        const float q0 = q[qbase + lane];
        const float q1 = q[qbase + lane + 32];

        float m = -INFINITY;
        float l = 0.f;
        float acc0 = 0.f, acc1 = 0.f;

        for (int j = 0; j < SEG_LEN; j++) {
            const int kpos = i + j * step;
            if (causal && kpos > qpos) break;  // monotone -> all later keys masked

            const size_t kb = ((size_t)kpos * NH + h) * ND;
            float s = q0 * k[kb + lane] + q1 * k[kb + lane + 32];
            #pragma unroll
            for (int off = 16; off; off >>= 1)
                s += __shfl_xor_sync(0xffffffffu, s, off);
            s *= scale;

            const float mnew = fmaxf(m, s);
            const float corr = expf(m - mnew);   // 0 on first iter (m = -inf)
            const float p    = expf(s - mnew);
            l    = l * corr + p;
            acc0 = acc0 * corr + p * v[kb + lane];
            acc1 = acc1 * corr + p * v[kb + lane + 32];
            m = mnew;
        }

        const float inv = 1.f / l;
        out[qbase + lane]      = acc0 * inv;
        out[qbase + lane + 32] = acc1 * inv;
    } else {
        // ------------------- zero-fill path -------------------
        // Fill [ATTN_FLOATS, out_elems) with zeros, vectorized float4.
        float4* __restrict__ dst = (float4*)(out + ATTN_FLOATS);
        const int nvec = (out_elems - ATTN_FLOATS) >> 2;
        const int zb = blockIdx.x - ATTN_BLOCKS;
        const float4 z = make_float4(0.f, 0.f, 0.f, 0.f);
        for (int idx = zb * THREADS + threadIdx.x; idx < nvec;
             idx += ZERO_BLOCKS * THREADS) {
            dst[idx] = z;
        }
    }
}

extern "C" void kernel_launch(void* const* d_in, const int* in_sizes, int n_in,
                              void* d_out, int out_size) {
    const float* q = (const float*)d_in[0];
    const float* k = (const float*)d_in[1];
    const float* v = (const float*)d_in[2];
    const int* is_causal = (const int*)d_in[3];
    float* out = (float*)d_out;

    fused_kernel<<<ATTN_BLOCKS + ZERO_BLOCKS, THREADS>>>(q, k, v, is_causal,
                                                         out, out_size);
}

// round 4
// speedup vs baseline: 1.1440x; 1.0864x over previous
#include <cuda_runtime.h>
#include <math.h>

#define NH 16
#define ND 64
#define SEG_LEN 128

// Attention region: rows 0..255 -> 256*NH*ND floats = 262144 (1 MB)
#define ATTN_FLOATS (256 * NH * ND)

#define ATTN_BLOCKS 64          // 8 warps/block * 64 ... see below: need 4096 warps
#define THREADS 256

// 4096 (q,h) warps / 8 warps per block = 512 attention blocks
#define ATTN_CTAS 512
// zero region: 33554432 - 262144 = 33292288 floats = 8323072 float4
// 8323072 / 256 threads = 32512 CTAs, exactly one float4 store per thread
#define ZERO_CTAS 32512

// ---------------------------------------------------------------------------
// Fused kernel:
//   blocks [0, ATTN_CTAS)    -> dilated attention (writes rows 0..255)
//   blocks [ATTN_CTAS, ...)  -> zero-fill, ONE float4 per thread (no loop)
// ---------------------------------------------------------------------------
__global__ void fused_kernel(const float* __restrict__ q,
                             const float* __restrict__ k,
                             const float* __restrict__ v,
                             const int* __restrict__ is_causal_ptr,
                             float* __restrict__ out) {
    if (blockIdx.x >= ATTN_CTAS) {
        // ------------------- zero-fill path (bulk of the grid) -------------
        const int idx = (blockIdx.x - ATTN_CTAS) * THREADS + threadIdx.x;
        float4* __restrict__ dst = (float4*)(out + ATTN_FLOATS);
        dst[idx] = make_float4(0.f, 0.f, 0.f, 0.f);
        return;
    }

    // ------------------- attention path -------------------
    const int w    = blockIdx.x * (THREADS / 32) + (threadIdx.x >> 5); // 0..4095
    const int lane = threadIdx.x & 31;
    const int qh   = w & 255;          // seg*128 + i
    const int h    = w >> 8;           // 0..15
    const int seg  = qh >> 7;
    const int i    = qh & 127;
    const int seg_start = seg * SEG_LEN;
    const int step = SEG_LEN << seg;   // 128 (seg 0) or 256 (seg 1)
    const int qpos = seg_start + i;
    const int causal = is_causal_ptr[0];
    const float scale = 0.125f;        // 1/sqrt(64)

    const size_t qbase = ((size_t)qpos * NH + h) * ND;
    const float q0 = q[qbase + lane];
    const float q1 = q[qbase + lane + 32];

    float m = -INFINITY;
    float l = 0.f;
    float acc0 = 0.f, acc1 = 0.f;

    for (int j = 0; j < SEG_LEN; j++) {
        const int kpos = i + j * step;
        if (causal && kpos > qpos) break;  // monotone -> all later keys masked

        const size_t kb = ((size_t)kpos * NH + h) * ND;
        float s = q0 * k[kb + lane] + q1 * k[kb + lane + 32];
        #pragma unroll
        for (int off = 16; off; off >>= 1)
            s += __shfl_xor_sync(0xffffffffu, s, off);
        s *= scale;

        const float mnew = fmaxf(m, s);
        const float corr = expf(m - mnew);   // 0 on first iter (m = -inf)
        const float p    = expf(s - mnew);
        l    = l * corr + p;
        acc0 = acc0 * corr + p * v[kb + lane];
        acc1 = acc1 * corr + p * v[kb + lane + 32];
        m = mnew;
    }

    const float inv = 1.f / l;
    out[qbase + lane]      = acc0 * inv;
    out[qbase + lane + 32] = acc1 * inv;
}

extern "C" void kernel_launch(void* const* d_in, const int* in_sizes, int n_in,
                              void* d_out, int out_size) {
    const float* q = (const float*)d_in[0];
    const float* k = (const float*)d_in[1];
    const float* v = (const float*)d_in[2];
    const int* is_causal = (const int*)d_in[3];
    float* out = (float*)d_out;

    (void)out_size;  // shape is fixed by the problem: 1*32768*16*64 floats
    fused_kernel<<<ATTN_CTAS + ZERO_CTAS, THREADS>>>(q, k, v, is_causal, out);
}

// round 5
// speedup vs baseline: 1.1488x; 1.0041x over previous
#include <cuda_runtime.h>
#include <math.h>

#define NH 16
#define ND 64
#define SEG_LEN 128

// Attention region: rows 0..255 -> 256*NH*ND floats = 262144 (1 MB)
#define ATTN_FLOATS (256 * NH * ND)

#define THREADS 256
// zero region: 33554432 - 262144 = 33292288 floats = 8323072 float4
// = 32512 CTAs x 256 threads, exactly one float4 store per thread
#define ZERO_CTAS 32512
// 4096 (q,h) warps / 8 warps per block = 512 attention CTAs, placed LAST
#define ATTN_CTAS 512

// ---------------------------------------------------------------------------
// Fused kernel:
//   blocks [0, ZERO_CTAS)  -> zero-fill, one streaming float4 store per thread
//   blocks [ZERO_CTAS, +ATTN_CTAS) -> dilated attention (writes rows 0..255)
// Zero CTAs lead so the write stream ramps with uniform CTAs; the small
// latency-bound attention runs in the final wave, hidden under store drain.
// ---------------------------------------------------------------------------
__global__ void fused_kernel(const float* __restrict__ q,
                             const float* __restrict__ k,
                             const float* __restrict__ v,
                             const int* __restrict__ is_causal_ptr,
                             float* __restrict__ out) {
    if (blockIdx.x < ZERO_CTAS) {
        // ------------------- zero-fill path (bulk of the grid) -------------
        const int idx = blockIdx.x * THREADS + threadIdx.x;
        float4* __restrict__ dst = (float4*)(out + ATTN_FLOATS);
        __stcs(dst + idx, make_float4(0.f, 0.f, 0.f, 0.f));
        return;
    }

    // ------------------- attention path (last 512 CTAs) -------------------
    const int w    = (blockIdx.x - ZERO_CTAS) * (THREADS / 32) + (threadIdx.x >> 5);
    const int lane = threadIdx.x & 31;
    const int qh   = w & 255;          // seg*128 + i
    const int h    = w >> 8;           // 0..15
    const int seg  = qh >> 7;
    const int i    = qh & 127;
    const int seg_start = seg * SEG_LEN;
    const int step = SEG_LEN << seg;   // 128 (seg 0) or 256 (seg 1)
    const int qpos = seg_start + i;
    const int causal = is_causal_ptr[0];
    const float scale = 0.125f;        // 1/sqrt(64)

    const size_t qbase = ((size_t)qpos * NH + h) * ND;
    const float q0 = q[qbase + lane];
    const float q1 = q[qbase + lane + 32];

    float m = -INFINITY;
    float l = 0.f;
    float acc0 = 0.f, acc1 = 0.f;

    for (int j = 0; j < SEG_LEN; j++) {
        const int kpos = i + j * step;
        if (causal && kpos > qpos) break;  // monotone -> all later keys masked

        const size_t kb = ((size_t)kpos * NH + h) * ND;
        // issue all 4 loads up front so they overlap the shfl/exp chain
        const float k0 = k[kb + lane];
        const float k1 = k[kb + lane + 32];
        const float v0 = v[kb + lane];
        const float v1 = v[kb + lane + 32];

        float s = q0 * k0 + q1 * k1;
        #pragma unroll
        for (int off = 16; off; off >>= 1)
            s += __shfl_xor_sync(0xffffffffu, s, off);
        s *= scale;

        const float mnew = fmaxf(m, s);
        const float corr = expf(m - mnew);   // 0 on first iter (m = -inf)
        const float p    = expf(s - mnew);
        l    = l * corr + p;
        acc0 = acc0 * corr + p * v0;
        acc1 = acc1 * corr + p * v1;
        m = mnew;
    }

    const float inv = 1.f / l;
    out[qbase + lane]      = acc0 * inv;
    out[qbase + lane + 32] = acc1 * inv;
}

extern "C" void kernel_launch(void* const* d_in, const int* in_sizes, int n_in,
                              void* d_out, int out_size) {
    const float* q = (const float*)d_in[0];
    const float* k = (const float*)d_in[1];
    const float* v = (const float*)d_in[2];
    const int* is_causal = (const int*)d_in[3];
    float* out = (float*)d_out;

    (void)out_size;  // shape fixed by the problem: 1*32768*16*64 floats
    fused_kernel<<<ZERO_CTAS + ATTN_CTAS, THREADS>>>(q, k, v, is_causal, out);
}